// round 1
// baseline (speedup 1.0000x reference)
#include <cuda_runtime.h>
#include <cstdint>

#define FG_IOU 0.7f
#define BG_IOU 0.3f
#define IMG    640.0f

// Scratch for per-(b,g) best-anchor packed keys:  (iou_bits << 32) | ~anchor_idx
__device__ unsigned long long g_best[8192];

__global__ void init_best_kernel(int n) {
    int i = blockIdx.x * blockDim.x + threadIdx.x;
    if (i < n) g_best[i] = 0ULL;
}

// Main pass: one thread handles 2 anchors; gts live in smem.
// Computes rules 2 & 3 + max_iou directly; accumulates per-gt best anchor
// (rule 1 candidate) via block smem atomicMax then a filtered global atomicMax.
__global__ __launch_bounds__(256) void assign_main_kernel(
    const float4* __restrict__ anchors,   // [B,A] cxcywh
    const float4* __restrict__ gts,       // [B,G] xyxy
    float*  __restrict__ out_labels,      // [B,A]  (float-encoded int)
    float4* __restrict__ out_matched,     // [B,A]
    float*  __restrict__ out_maxiou,      // [B,A]
    int A, int G)
{
    __shared__ float4 sgt[128];
    __shared__ float  sarea[128];
    __shared__ unsigned long long spm[128];

    const int b = blockIdx.y;
    const int t = threadIdx.x;

    if (t < G) {
        float4 g = gts[b * G + t];
        sgt[t]   = g;
        sarea[t] = (g.z - g.x) * (g.w - g.y);
        spm[t]   = 0ULL;
    }
    __syncthreads();

    const int base = blockIdx.x * 512;
    int  aidx[2];
    bool valid[2];
    float ax1[2], ay1[2], ax2[2], ay2[2], area[2], best[2];
    int bestg[2];
    unsigned int inv[2];

    aidx[0] = base + t;
    aidx[1] = base + 256 + t;

#pragma unroll
    for (int k = 0; k < 2; k++) {
        valid[k] = (aidx[k] < A);
        int a = valid[k] ? aidx[k] : (A - 1);
        float4 an = anchors[(long long)b * A + a];
        ax1[k] = an.x - 0.5f * an.z;
        ay1[k] = an.y - 0.5f * an.w;
        ax2[k] = an.x + 0.5f * an.z;
        ay2[k] = an.y + 0.5f * an.w;
        // area from xyxy (matches reference rounding path)
        area[k] = (ax2[k] - ax1[k]) * (ay2[k] - ay1[k]);
        best[k] = -1.0f;
        bestg[k] = 0;
        inv[k] = ~(unsigned int)a;   // larger inv == smaller index -> first-occurrence tiebreak
    }

#pragma unroll 16
    for (int g = 0; g < G; g++) {
        const float4 gb = sgt[g];
        const float  ga = sarea[g];
        const unsigned long long cur = spm[g];   // racy read; filter is conservative-safe
        float iou[2];
#pragma unroll
        for (int k = 0; k < 2; k++) {
            float ltx = fmaxf(ax1[k], gb.x);
            float lty = fmaxf(ay1[k], gb.y);
            float rbx = fminf(ax2[k], gb.z);
            float rby = fminf(ay2[k], gb.w);
            float w = fmaxf(rbx - ltx, 0.0f);
            float h = fmaxf(rby - lty, 0.0f);
            float inter = w * h;
            float uni = (area[k] + ga) - inter;   // > 0 always (areas >= 16x16)
            iou[k] = __fdividef(inter, uni);
            if (iou[k] > best[k]) { best[k] = iou[k]; bestg[k] = g; }  // strict > => first max
        }
#pragma unroll
        for (int k = 0; k < 2; k++) {
            unsigned long long key =
                ((unsigned long long)(unsigned int)__float_as_int(iou[k]) << 32)
                | (unsigned long long)inv[k];
            if (key > cur) atomicMax(&spm[g], key);
        }
    }

    // Per-anchor epilogue: rules 2 & 3 + cross filter, write outputs.
#pragma unroll
    for (int k = 0; k < 2; k++) {
        if (!valid[k]) continue;
        float mv = best[k];
        bool fg = mv > FG_IOU;
        int lab = fg ? 1 : ((mv < BG_IOU) ? 0 : -1);
        bool cross = (ax1[k] < 0.0f) | (ay1[k] < 0.0f) | (ax2[k] > IMG) | (ay2[k] > IMG);
        if (cross) lab = -1;                      // cross filter affects labels only
        float4 m = make_float4(0.f, 0.f, 0.f, 0.f);
        if (fg) m = sgt[bestg[k]];                // rule 2 matched box
        long long o = (long long)b * A + aidx[k];
        out_labels[o]  = (float)lab;
        out_matched[o] = m;
        out_maxiou[o]  = mv;
    }

    // Flush block-best keys to global, filtered through an L2 read (safe: stale
    // reads are only ever smaller, so we may do a redundant atomic, never skip one).
    __syncthreads();
    if (t < G) {
        unsigned long long v = spm[t];
        unsigned long long* p = &g_best[b * G + t];
        unsigned long long cur;
        asm volatile("ld.global.cg.u64 %0, [%1];" : "=l"(cur) : "l"(p));
        if (v > cur) atomicMax(p, v);
    }
}

// Rule 1 apply. Reference order: rule1 sets label/matched, THEN rule2 overrides
// matched where fg, THEN cross filter zaps labels. Equivalent post-pass:
//   label[best_a] = cross ? -1 : 1   (always)
//   matched[best_a] = gt[g]          (only where NOT fg)
// One block per batch; parallel gather, serial ascending-g writes so duplicate
// best-anchors resolve deterministically (last g wins, like the scatter).
__global__ void apply_rule1_kernel(
    const float4* __restrict__ anchors,
    const float4* __restrict__ gts,
    float*  __restrict__ out_labels,
    float4* __restrict__ out_matched,
    const float* __restrict__ out_maxiou,
    int A, int G)
{
    __shared__ int   s_a[128];
    __shared__ float s_lab[128];
    __shared__ int   s_fg[128];

    int b = blockIdx.x;
    int g = threadIdx.x;
    if (g < G) {
        unsigned long long v = g_best[b * G + g];
        unsigned int a = ~(unsigned int)(v & 0xFFFFFFFFull);
        if (a < (unsigned)A) {
            float mv = out_maxiou[(long long)b * A + a];
            float4 an = anchors[(long long)b * A + a];
            float x1 = an.x - 0.5f * an.z, y1 = an.y - 0.5f * an.w;
            float x2 = an.x + 0.5f * an.z, y2 = an.y + 0.5f * an.w;
            bool cross = (x1 < 0.0f) || (y1 < 0.0f) || (x2 > IMG) || (y2 > IMG);
            s_a[g]   = (int)a;
            s_lab[g] = cross ? -1.0f : 1.0f;
            s_fg[g]  = (mv > FG_IOU) ? 1 : 0;
        } else {
            s_a[g] = -1;
        }
    }
    __syncthreads();
    if (g == 0) {
        for (int j = 0; j < G; j++) {
            int a = s_a[j];
            if (a < 0) continue;
            long long o = (long long)b * A + a;
            out_labels[o] = s_lab[j];
            if (!s_fg[j]) out_matched[o] = gts[b * G + j];
        }
    }
}

extern "C" void kernel_launch(void* const* d_in, const int* in_sizes, int n_in,
                              void* d_out, int out_size)
{
    const float4* anchors = (const float4*)d_in[0];   // [B,A,4] cxcywh
    const float4* gts     = (const float4*)d_in[1];   // [B,G,4] xyxy

    const int G = 64;
    int nA = in_sizes[0];
    int nG = in_sizes[1];
    int B  = nG / (G * 4);
    int A  = nA / (B * 4);

    float*  out         = (float*)d_out;
    float*  out_labels  = out;                                  // [B*A]
    float4* out_matched = (float4*)(out + (long long)B * A);    // [B*A] float4
    float*  out_maxiou  = out + (long long)B * A * 5;           // [B*A]

    init_best_kernel<<<(B * G + 255) / 256, 256>>>(B * G);

    dim3 grid((A + 511) / 512, B);
    assign_main_kernel<<<grid, 256>>>(anchors, gts, out_labels, out_matched,
                                      out_maxiou, A, G);

    apply_rule1_kernel<<<B, 128>>>(anchors, gts, out_labels, out_matched,
                                   out_maxiou, A, G);
}

// round 2
// speedup vs baseline: 1.0786x; 1.0786x over previous
#include <cuda_runtime.h>
#include <cstdint>

#define FG_IOU 0.7f
#define BG_IOU 0.3f
#define IMG    640.0f

// Scratch for per-(b,g) best-anchor packed keys: (iou_bits << 32) | ~anchor_idx.
// Zero-initialized at module load; apply_rule1_kernel resets it to zero after
// consuming, so every kernel_launch call starts from a clean state.
__device__ unsigned long long g_best[8192];

// Main pass: 4 anchors per thread (block covers 1024 anchors); 64 gts in smem.
// Rules 2 & 3 + max_iou computed directly. Rule-1 candidates (per-gt argmax over
// anchors) tracked via a float-bits threshold in smem: per pair only one 32-bit
// compare; the 64-bit packed-key atomicMax runs on a ballot-gated rare path.
__global__ __launch_bounds__(256) void assign_main_kernel(
    const float4* __restrict__ anchors,   // [B,A] cxcywh
    const float4* __restrict__ gts,       // [B,G] xyxy
    float*  __restrict__ out_labels,      // [B,A]
    float4* __restrict__ out_matched,     // [B,A]
    float*  __restrict__ out_maxiou,      // [B,A]
    int A, int G)
{
    __shared__ float4 sgt[64];
    __shared__ float  sarea[64];
    __shared__ unsigned long long spm[64];   // packed (iou_bits<<32)|~a, block-local running max

    const int b = blockIdx.y;
    const int t = threadIdx.x;

    if (t < G) {
        float4 g = gts[b * G + t];
        sgt[t]   = g;
        sarea[t] = (g.z - g.x) * (g.w - g.y);
        spm[t]   = 0ULL;
    }
    __syncthreads();

    const int base = blockIdx.x * 1024;
    const long long abase = (long long)b * A;

    float ax1[4], ay1[4], ax2[4], ay2[4], area[4], best[4];
    int   bestg[4], aidx[4];
    unsigned inv[4];

#pragma unroll
    for (int k = 0; k < 4; k++) {
        int a = base + k * 256 + t;
        aidx[k] = a;
        if (a >= A) a = A - 1;                // A % 1024 == 0 in practice; safety only
        float4 an = __ldg(&anchors[abase + a]);
        ax1[k] = an.x - 0.5f * an.z;
        ay1[k] = an.y - 0.5f * an.w;
        ax2[k] = an.x + 0.5f * an.z;
        ay2[k] = an.y + 0.5f * an.w;
        area[k] = (ax2[k] - ax1[k]) * (ay2[k] - ay1[k]);
        best[k] = -1.0f;
        bestg[k] = 0;
        inv[k] = ~(unsigned)a;                // larger inv == smaller index -> first-occurrence tiebreak
    }

#pragma unroll 4
    for (int g = 0; g < G; g++) {
        const float4 gb = sgt[g];
        const float  ga = sarea[g];
        // Racy read of the high word (current best iou bits) — stale values are
        // only ever smaller, so the filter is conservative-safe. Non-negative
        // float bits compare correctly as unsigned ints.
        const unsigned thr = ((const volatile unsigned*)&spm[g])[1];

        unsigned ib[4];
        bool anypass = false;
#pragma unroll
        for (int k = 0; k < 4; k++) {
            float ltx = fmaxf(ax1[k], gb.x);
            float lty = fmaxf(ay1[k], gb.y);
            float rbx = fminf(ax2[k], gb.z);
            float rby = fminf(ay2[k], gb.w);
            float w = fmaxf(rbx - ltx, 0.0f);
            float h = fmaxf(rby - lty, 0.0f);
            float inter = w * h;
            float uni = (area[k] + ga) - inter;     // > 0 always (boxes have area)
            float iou = __fdividef(inter, uni);
            if (iou > best[k]) { best[k] = iou; bestg[k] = g; }  // strict > => first max
            ib[k] = __float_as_uint(iou);
            anypass |= (ib[k] > thr);
        }
        // Uniform branch: entire warp takes the rare path together.
        if (__ballot_sync(0xFFFFFFFFu, anypass)) {
#pragma unroll
            for (int k = 0; k < 4; k++) {
                if (ib[k] > thr)
                    atomicMax(&spm[g],
                              ((unsigned long long)ib[k] << 32) | (unsigned long long)inv[k]);
            }
        }
    }

    // Per-anchor epilogue: rules 2 & 3 + cross filter.
#pragma unroll
    for (int k = 0; k < 4; k++) {
        if (aidx[k] >= A) continue;
        float mv = best[k];
        bool fg = mv > FG_IOU;
        int lab = fg ? 1 : ((mv < BG_IOU) ? 0 : -1);
        bool cross = (ax1[k] < 0.0f) | (ay1[k] < 0.0f) | (ax2[k] > IMG) | (ay2[k] > IMG);
        if (cross) lab = -1;                       // cross filter affects labels only
        float4 m = make_float4(0.f, 0.f, 0.f, 0.f);
        if (fg) m = sgt[bestg[k]];                 // rule-2 matched box
        long long o = abase + aidx[k];
        out_labels[o]  = (float)lab;
        out_matched[o] = m;
        out_maxiou[o]  = mv;
    }

    // Flush block-best keys to global, filtered through an L2 read (stale reads
    // are only smaller -> possibly redundant atomic, never a skipped one).
    __syncthreads();
    if (t < G) {
        unsigned long long v = spm[t];
        unsigned long long* p = &g_best[b * G + t];
        unsigned long long cur;
        asm volatile("ld.global.cg.u64 %0, [%1];" : "=l"(cur) : "l"(p));
        if (v > cur) atomicMax(p, v);
    }
}

// Rule-1 apply. Reference order: rule1 sets label/matched, THEN rule2 overrides
// matched where fg, THEN cross filter zaps labels. Equivalent post-pass:
//   label[best_a]   = cross ? -1 : 1   (always)
//   matched[best_a] = gt[g]            (only where NOT fg)
// One block per batch; parallel gather, serial ascending-g writes for
// deterministic duplicate resolution. Also resets g_best for the next call.
__global__ void apply_rule1_kernel(
    const float4* __restrict__ anchors,
    const float4* __restrict__ gts,
    float*  __restrict__ out_labels,
    float4* __restrict__ out_matched,
    const float* __restrict__ out_maxiou,
    int A, int G)
{
    __shared__ int   s_a[64];
    __shared__ float s_lab[64];
    __shared__ int   s_fg[64];

    int b = blockIdx.x;
    int g = threadIdx.x;
    if (g < G) {
        unsigned long long v = g_best[b * G + g];
        g_best[b * G + g] = 0ULL;                  // reset scratch for next launch
        unsigned a = ~(unsigned)(v & 0xFFFFFFFFull);
        if (a < (unsigned)A) {
            float mv = out_maxiou[(long long)b * A + a];
            float4 an = anchors[(long long)b * A + a];
            float x1 = an.x - 0.5f * an.z, y1 = an.y - 0.5f * an.w;
            float x2 = an.x + 0.5f * an.z, y2 = an.y + 0.5f * an.w;
            bool cross = (x1 < 0.0f) || (y1 < 0.0f) || (x2 > IMG) || (y2 > IMG);
            s_a[g]   = (int)a;
            s_lab[g] = cross ? -1.0f : 1.0f;
            s_fg[g]  = (mv > FG_IOU) ? 1 : 0;
        } else {
            s_a[g] = -1;
        }
    }
    __syncthreads();
    if (g == 0) {
        for (int j = 0; j < G; j++) {
            int a = s_a[j];
            if (a < 0) continue;
            long long o = (long long)b * A + a;
            out_labels[o] = s_lab[j];
            if (!s_fg[j]) out_matched[o] = gts[b * G + j];
        }
    }
}

extern "C" void kernel_launch(void* const* d_in, const int* in_sizes, int n_in,
                              void* d_out, int out_size)
{
    const float4* anchors = (const float4*)d_in[0];   // [B,A,4] cxcywh
    const float4* gts     = (const float4*)d_in[1];   // [B,G,4] xyxy

    const int G = 64;
    int nA = in_sizes[0];
    int nG = in_sizes[1];
    int B  = nG / (G * 4);
    int A  = nA / (B * 4);

    float*  out         = (float*)d_out;
    float*  out_labels  = out;                                  // [B*A]
    float4* out_matched = (float4*)(out + (long long)B * A);    // [B*A] float4
    float*  out_maxiou  = out + (long long)B * A * 5;           // [B*A]

    dim3 grid((A + 1023) / 1024, B);
    assign_main_kernel<<<grid, 256>>>(anchors, gts, out_labels, out_matched,
                                      out_maxiou, A, G);

    apply_rule1_kernel<<<B, 64>>>(anchors, gts, out_labels, out_matched,
                                  out_maxiou, A, G);
}

// round 4
// speedup vs baseline: 1.4020x; 1.2998x over previous
#include <cuda_runtime.h>
#include <cstdint>

#define FG_IOU 0.7f
#define BG_IOU 0.3f
#define IMG    640.0f

// Scratch for per-(b,g) best-anchor packed keys: (iou_bits << 32) | ~anchor_idx.
// Zero-initialized at module load; apply_rule1_kernel resets it to zero after
// consuming, so every kernel_launch call starts from a clean state.
__device__ unsigned long long g_best[8192];

// Main pass: 4 anchors per thread (block covers 1024 anchors); 64 gts in smem.
// Rules 2 & 3 + max_iou computed directly. Rule-1 candidates (per-gt argmax
// over anchors) tracked via block-local running max in smem, seeded from the
// global running max, with a REDUX.MAX-gated atomic path.
__global__ __launch_bounds__(256) void assign_main_kernel(
    const float4* __restrict__ anchors,   // [B,A] cxcywh
    const float4* __restrict__ gts,       // [B,G] xyxy
    float*  __restrict__ out_labels,      // [B,A]
    float4* __restrict__ out_matched,     // [B,A]
    float*  __restrict__ out_maxiou,      // [B,A]
    int A, int G)
{
    __shared__ float4 sgt[64];
    __shared__ float  sarea[64];
    __shared__ unsigned long long spm[64];   // packed (iou_bits<<32)|~a, block running max

    const int b = blockIdx.y;
    const int t = threadIdx.x;

    if (t < G) {
        float4 g = gts[b * G + t];
        sgt[t]   = g;
        sarea[t] = (g.z - g.x) * (g.w - g.y);
        // Seed from global running max (other blocks' progress). Racy/stale reads
        // are only smaller -> conservative-safe; final result unaffected.
        unsigned long long seed;
        asm volatile("ld.global.cg.u64 %0, [%1];" : "=l"(seed) : "l"(&g_best[b * G + t]));
        spm[t] = seed;
    }
    __syncthreads();

    const int base = blockIdx.x * 1024;
    const long long abase = (long long)b * A;

    float ax1[4], ay1[4], ax2[4], ay2[4], area[4], best[4];
    int   bestg[4], aidx[4];
    unsigned inv[4];

#pragma unroll
    for (int k = 0; k < 4; k++) {
        int a = base + k * 256 + t;
        aidx[k] = a;
        if (a >= A) a = A - 1;                // A % 1024 == 0 in practice; safety only
        float4 an = __ldg(&anchors[abase + a]);
        ax1[k] = an.x - 0.5f * an.z;
        ay1[k] = an.y - 0.5f * an.w;
        ax2[k] = an.x + 0.5f * an.z;
        ay2[k] = an.y + 0.5f * an.w;
        area[k] = (ax2[k] - ax1[k]) * (ay2[k] - ay1[k]);
        best[k] = -1.0f;
        bestg[k] = 0;
        inv[k] = ~(unsigned)a;                // larger inv == smaller index -> first-occurrence tiebreak
    }

#pragma unroll 4
    for (int g = 0; g < G; g++) {
        const float4 gb = sgt[g];
        const float  ga = sarea[g];
        // Racy snapshot of current block-best iou bits (non-negative float bits
        // order as u32). Stale => smaller => conservative-safe.
        const unsigned thr = ((const volatile unsigned*)&spm[g])[1];

        float iou[4];
        float mx = 0.0f;                       // iou >= 0; 0 never beats thr meaningfully
#pragma unroll
        for (int k = 0; k < 4; k++) {
            float ltx = fmaxf(ax1[k], gb.x);
            float lty = fmaxf(ay1[k], gb.y);
            float rbx = fminf(ax2[k], gb.z);
            float rby = fminf(ay2[k], gb.w);
            float w = fmaxf(rbx - ltx, 0.0f);
            float h = fmaxf(rby - lty, 0.0f);
            float inter = w * h;
            float uni = (area[k] + ga) - inter;      // > 0 always (boxes have area)
            iou[k] = __fdividef(inter, uni);
            if (iou[k] > best[k]) { best[k] = iou[k]; bestg[k] = g; }  // strict > => first max
            mx = fmaxf(mx, iou[k]);
        }
        // Single HW warp reduction; branch is warp-uniform.
        unsigned wmax = __reduce_max_sync(0xFFFFFFFFu, __float_as_uint(mx));
        if (wmax > thr) {
#pragma unroll
            for (int k = 0; k < 4; k++) {
                if (__float_as_uint(iou[k]) == wmax)
                    atomicMax(&spm[g],
                              ((unsigned long long)wmax << 32) | (unsigned long long)inv[k]);
            }
        }
    }

    // Per-anchor epilogue: rules 2 & 3 + cross filter.
#pragma unroll
    for (int k = 0; k < 4; k++) {
        if (aidx[k] >= A) continue;
        float mv = best[k];
        bool fg = mv > FG_IOU;
        int lab = fg ? 1 : ((mv < BG_IOU) ? 0 : -1);
        bool cross = (ax1[k] < 0.0f) | (ay1[k] < 0.0f) | (ax2[k] > IMG) | (ay2[k] > IMG);
        if (cross) lab = -1;                       // cross filter affects labels only
        float4 m = make_float4(0.f, 0.f, 0.f, 0.f);
        if (fg) m = sgt[bestg[k]];                 // rule-2 matched box
        long long o = abase + aidx[k];
        out_labels[o]  = (float)lab;
        out_matched[o] = m;
        out_maxiou[o]  = mv;
    }

    // Flush block-best keys to global, filtered through an L2 read (stale reads
    // are only smaller -> possibly redundant atomic, never a skipped one).
    __syncthreads();
    if (t < G) {
        unsigned long long v = spm[t];
        unsigned long long* p = &g_best[b * G + t];
        unsigned long long cur;
        asm volatile("ld.global.cg.u64 %0, [%1];" : "=l"(cur) : "l"(p));
        if (v > cur) atomicMax(p, v);
    }
}

// Rule-1 apply. Reference order: rule1 sets label/matched, THEN rule2 overrides
// matched where fg, THEN cross filter zaps labels. Equivalent post-pass:
//   label[best_a]   = cross ? -1 : 1   (always)
//   matched[best_a] = gt[g]            (only where NOT fg)
// Fully parallel: duplicate best-anchors resolved by last-g-wins via an O(G^2)
// smem scan (labels are identical for duplicates: they depend only on the
// anchor). Also resets g_best for the next launch.
__global__ void apply_rule1_kernel(
    const float4* __restrict__ anchors,
    const float4* __restrict__ gts,
    float*  __restrict__ out_labels,
    float4* __restrict__ out_matched,
    const float* __restrict__ out_maxiou,
    int A, int G)
{
    __shared__ int s_a[64];

    int b = blockIdx.x;
    int g = threadIdx.x;

    int   a_idx = -1;
    float lab   = 0.0f;
    int   fg    = 0;
    float4 gt   = make_float4(0.f, 0.f, 0.f, 0.f);

    if (g < G) {
        unsigned long long v = g_best[b * G + g];
        g_best[b * G + g] = 0ULL;                  // reset scratch for next launch
        unsigned a = ~(unsigned)(v & 0xFFFFFFFFull);
        if (a < (unsigned)A) {
            a_idx = (int)a;
            float mv = out_maxiou[(long long)b * A + a];
            float4 an = anchors[(long long)b * A + a];
            float x1 = an.x - 0.5f * an.z, y1 = an.y - 0.5f * an.w;
            float x2 = an.x + 0.5f * an.z, y2 = an.y + 0.5f * an.w;
            bool cross = (x1 < 0.0f) || (y1 < 0.0f) || (x2 > IMG) || (y2 > IMG);
            lab = cross ? -1.0f : 1.0f;
            fg  = (mv > FG_IOU) ? 1 : 0;
            gt  = gts[b * G + g];
        }
        s_a[g] = a_idx;
    }
    __syncthreads();

    if (g < G && a_idx >= 0) {
        // Later g with the same anchor wins (matches serialized scatter order).
        bool later_dup = false;
        for (int j = g + 1; j < G; j++) later_dup |= (s_a[j] == a_idx);
        if (!later_dup) {
            long long o = (long long)b * A + a_idx;
            out_labels[o] = lab;
            if (!fg) out_matched[o] = gt;
        }
    }
}

extern "C" void kernel_launch(void* const* d_in, const int* in_sizes, int n_in,
                              void* d_out, int out_size)
{
    const float4* anchors = (const float4*)d_in[0];   // [B,A,4] cxcywh
    const float4* gts     = (const float4*)d_in[1];   // [B,G,4] xyxy

    const int G = 64;
    int nA = in_sizes[0];
    int nG = in_sizes[1];
    int B  = nG / (G * 4);
    int A  = nA / (B * 4);

    float*  out         = (float*)d_out;
    float*  out_labels  = out;                                  // [B*A]
    float4* out_matched = (float4*)(out + (long long)B * A);    // [B*A] float4
    float*  out_maxiou  = out + (long long)B * A * 5;           // [B*A]

    dim3 grid((A + 1023) / 1024, B);
    assign_main_kernel<<<grid, 256>>>(anchors, gts, out_labels, out_matched,
                                      out_maxiou, A, G);

    apply_rule1_kernel<<<B, 64>>>(anchors, gts, out_labels, out_matched,
                                  out_maxiou, A, G);
}